// round 14
// baseline (speedup 1.0000x reference)
#include <cuda_runtime.h>
#include <cuda_fp16.h>
#include <cstdint>

// Problem constants
#define B_   4
#define T_   2048
#define C_   1024
#define H_   16
#define D_   64
#define TC3  (3 * C_)

// Scratch (allocation-free rule: __device__ globals), fp16 pipeline
__device__ __half g_qkv[B_ * T_ * TC3];    // [B,T,3C] k|q (v slot unused), q pre-scaled by 2^-5*log2e
__device__ __half g_vT[B_ * C_ * T_];      // [B][H*D][T]  V transposed
__device__ __half g_att[B_ * T_ * C_];     // [B,T,C]
__device__ __half g_xh[B_ * T_ * C_];      // [B,T,C]  x rounded to fp16
__device__ __half g_WqkvT[TC3 * C_];       // [3C, C] = W_qkv^T, q-rows pre-scaled
__device__ __half g_WprojT[C_ * C_];       // [C, C]  = W_proj^T

// ===========================================================================
// Helpers
// ===========================================================================
__device__ __forceinline__ uint32_t smem_to_u32(const void* p) {
    uint32_t a;
    asm("{ .reg .u64 t; cvta.to.shared.u64 t, %1; cvt.u32.u64 %0, t; }"
        : "=r"(a) : "l"(p));
    return a;
}

__device__ __forceinline__ void ldmx4(uint32_t* r, uint32_t addr) {
    asm volatile("ldmatrix.sync.aligned.m8n8.x4.shared.b16 {%0,%1,%2,%3}, [%4];"
                 : "=r"(r[0]), "=r"(r[1]), "=r"(r[2]), "=r"(r[3]) : "r"(addr));
}

__device__ __forceinline__ void mma_f16(float* c, const uint32_t* a,
                                        const uint32_t* b) {
    asm volatile(
        "mma.sync.aligned.m16n8k16.row.col.f32.f16.f16.f32 "
        "{%0,%1,%2,%3}, {%4,%5,%6,%7}, {%8,%9}, {%0,%1,%2,%3};"
        : "+f"(c[0]), "+f"(c[1]), "+f"(c[2]), "+f"(c[3])
        : "r"(a[0]), "r"(a[1]), "r"(a[2]), "r"(a[3]), "r"(b[0]), "r"(b[1]));
}

__device__ __forceinline__ void cp_async16(uint32_t smem_dst, const void* gsrc) {
    asm volatile("cp.async.cg.shared.global [%0], [%1], 16;"
                 :: "r"(smem_dst), "l"(gsrc));
}
#define CP_COMMIT() asm volatile("cp.async.commit_group;" ::: "memory")
#define CP_WAIT1()  asm volatile("cp.async.wait_group 1;" ::: "memory")
#define CP_WAIT0()  asm volatile("cp.async.wait_group 0;" ::: "memory")

#define SWZ(off) ((off) ^ (((off) >> 3) & 0x70))

__device__ __forceinline__ uint32_t h2u(__half2 h) {
    return *(uint32_t*)&h;
}

// ===========================================================================
// Round x to fp16 -> g_xh
// ===========================================================================
__global__ void round_x_kernel(const float* __restrict__ x)
{
    const int n8 = (B_ * T_ * C_) / 8;
    for (int i = blockIdx.x * blockDim.x + threadIdx.x; i < n8;
         i += gridDim.x * blockDim.x) {
        float4 v0 = ((const float4*)x)[2 * i];
        float4 v1 = ((const float4*)x)[2 * i + 1];
        uint4 o = { h2u(__floats2half2_rn(v0.x, v0.y)),
                    h2u(__floats2half2_rn(v0.z, v0.w)),
                    h2u(__floats2half2_rn(v1.x, v1.y)),
                    h2u(__floats2half2_rn(v1.z, v1.w)) };
        ((uint4*)g_xh)[i] = o;
    }
}

// ===========================================================================
// Weight transpose + fp16 round. MODE 0 scales q-rows (C..2C-1) by
// 2^-5 * log2(e) so S comes out of QK^T already in the exp2 domain.
// ===========================================================================
template <int MODE>
__global__ void transpose_kernel(const float* __restrict__ in, int R, int Cc)
{
    __shared__ float t[32][33];
    __half* out = (MODE == 0) ? (__half*)g_WqkvT : (__half*)g_WprojT;
    const int c0 = blockIdx.x * 32, r0 = blockIdx.y * 32;
#pragma unroll
    for (int j = threadIdx.y; j < 32; j += 8)
        t[j][threadIdx.x] = in[(size_t)(r0 + j) * Cc + c0 + threadIdx.x];
    __syncthreads();
#pragma unroll
    for (int j = threadIdx.y; j < 32; j += 8) {
        int orow = c0 + j;
        float v = t[threadIdx.x][j];
        if (MODE == 0 && orow >= C_ && orow < 2 * C_)
            v *= 0.03125f * 1.4426950408889634f;
        out[(size_t)orow * R + r0 + threadIdx.x] = __float2half_rn(v);
    }
}

// ===========================================================================
// fp16 tensor-core GEMM, cp.async 3-stage pipeline.
// CTA 256(M) x 128(N), 8 warps = 4(M) x 2(N), warp tile 64x64.
// Stage: A 256x128B (32KB) + B 128x128B (16KB) = 48KB; 3 stages = 144KB.
// MODE 0: A=g_xh, Bt=g_WqkvT; k,q -> g_qkv; v -> g_vT transposed.
// MODE 1: A=g_att, Bt=g_WprojT; C = param out (fp32).
// ===========================================================================
#define G2_STAGES 3
#define G2_ATILE  32768
#define G2_BTILE  16384
#define G2_STAGE_BYTES (G2_ATILE + G2_BTILE)
#define G2_SMEM   (G2_STAGES * G2_STAGE_BYTES)   // 147456

template <int K>
__device__ __forceinline__ void g2_issue(
    const __half* __restrict__ Ag, const __half* __restrict__ Bg,
    uint32_t Abuf, uint32_t Bbuf, int m0, int n0, int k0, int tid)
{
#pragma unroll
    for (int j = 0; j < 8; j++) {          // A: 256 rows x 8 chunks
        int slot = tid + j * 256;
        int row = slot >> 3;
        int f8  = slot & 7;
        cp_async16(Abuf + SWZ(row * 128 + f8 * 16),
                   Ag + (size_t)(m0 + row) * K + k0 + f8 * 8);
    }
#pragma unroll
    for (int j = 0; j < 4; j++) {          // B: 128 rows x 8 chunks
        int slot = tid + j * 256;
        int row = slot >> 3;
        int f8  = slot & 7;
        cp_async16(Bbuf + SWZ(row * 128 + f8 * 16),
                   Bg + (size_t)(n0 + row) * K + k0 + f8 * 8);
    }
}

template <int MODE, int N, int K>
__global__ __launch_bounds__(256, 1) void mma_gemm2(float* __restrict__ Cp)
{
    extern __shared__ char sm[];
    const uint32_t smem_u32 = smem_to_u32(sm);

    const __half* Ag = (MODE == 0) ? (const __half*)g_xh : (const __half*)g_att;
    const __half* Bg = (MODE == 0) ? (const __half*)g_WqkvT : (const __half*)g_WprojT;

    const int tid = threadIdx.x;
    const int lane = tid & 31;
    const int wid = tid >> 5;
    const int warp_m = wid >> 1;           // 0..3, 64-row slabs
    const int warp_n = wid & 1;            // 0..1, 64-col slabs
    const int m0 = blockIdx.y * 256;
    const int n0 = blockIdx.x * 128;

    float acc[4][8][4];
#pragma unroll
    for (int i = 0; i < 4; i++)
#pragma unroll
        for (int j = 0; j < 8; j++)
#pragma unroll
            for (int k = 0; k < 4; k++) acc[i][j][k] = 0.f;

    const int NCHUNK = K / 64;             // 16

    g2_issue<K>(Ag, Bg, smem_u32, smem_u32 + G2_ATILE, m0, n0, 0, tid);
    CP_COMMIT();
    g2_issue<K>(Ag, Bg, smem_u32 + G2_STAGE_BYTES,
                smem_u32 + G2_STAGE_BYTES + G2_ATILE, m0, n0, 64, tid);
    CP_COMMIT();

    const int a_row_in_tile = lane & 15;
    const int a_kblk = (lane >> 4) & 1;
    const int b_row_in_pair = ((lane & 16) >> 1) + (lane & 7);
    const int b_kblk = (lane >> 3) & 1;

    int st = 0;
    for (int i = 0; i < NCHUNK; i++) {
        CP_WAIT1();
        __syncthreads();

        if (i + 2 < NCHUNK) {
            int sn = st + 2; if (sn >= G2_STAGES) sn -= G2_STAGES;
            uint32_t base = smem_u32 + (uint32_t)sn * G2_STAGE_BYTES;
            g2_issue<K>(Ag, Bg, base, base + G2_ATILE, m0, n0, (i + 2) * 64, tid);
        }
        CP_COMMIT();

        const uint32_t Abuf = smem_u32 + (uint32_t)st * G2_STAGE_BYTES;
        const uint32_t Bbuf = Abuf + G2_ATILE;
#pragma unroll
        for (int ks = 0; ks < 4; ks++) {
            uint32_t afr[4][4];
#pragma unroll
            for (int mt = 0; mt < 4; mt++) {
                int row = warp_m * 64 + mt * 16 + a_row_in_tile;
                ldmx4(afr[mt], Abuf + SWZ(row * 128 + ks * 32 + a_kblk * 16));
            }
            uint32_t bfr[4][4];
#pragma unroll
            for (int p = 0; p < 4; p++) {
                int row = warp_n * 64 + p * 16 + b_row_in_pair;
                ldmx4(bfr[p], Bbuf + SWZ(row * 128 + ks * 32 + b_kblk * 16));
            }
#pragma unroll
            for (int mt = 0; mt < 4; mt++)
#pragma unroll
                for (int nt = 0; nt < 8; nt++)
                    mma_f16(acc[mt][nt], afr[mt], &bfr[nt >> 1][(nt & 1) * 2]);
        }

        if (++st == G2_STAGES) st = 0;
    }

    const int og = lane >> 2;
    const int ot = lane & 3;

    if (MODE == 0 && n0 >= 2 * C_) {
        // V block -> g_vT[B][H*D][T], transposed + fp16
#pragma unroll
        for (int mt = 0; mt < 4; mt++) {
            int r0 = m0 + warp_m * 64 + mt * 16 + og;
            int bb = r0 >> 11;
            int tt = r0 & (T_ - 1);
#pragma unroll
            for (int nt = 0; nt < 8; nt++) {
                int hd = n0 + warp_n * 64 + nt * 8 + ot * 2 - 2 * C_;
                __half* v0p = (__half*)g_vT + (size_t)(bb * C_ + hd) * T_;
                __half* v1p = v0p + T_;
                v0p[tt]     = __float2half_rn(acc[mt][nt][0]);
                v1p[tt]     = __float2half_rn(acc[mt][nt][1]);
                v0p[tt + 8] = __float2half_rn(acc[mt][nt][2]);
                v1p[tt + 8] = __float2half_rn(acc[mt][nt][3]);
            }
        }
    } else if (MODE == 0) {
        __half* Cg = (__half*)g_qkv;
#pragma unroll
        for (int mt = 0; mt < 4; mt++) {
            int r0 = m0 + warp_m * 64 + mt * 16 + og;
#pragma unroll
            for (int nt = 0; nt < 8; nt++) {
                int col = n0 + warp_n * 64 + nt * 8 + ot * 2;
                *(__half2*)(Cg + (size_t)r0 * N + col) =
                    __floats2half2_rn(acc[mt][nt][0], acc[mt][nt][1]);
                *(__half2*)(Cg + (size_t)(r0 + 8) * N + col) =
                    __floats2half2_rn(acc[mt][nt][2], acc[mt][nt][3]);
            }
        }
    } else {
#pragma unroll
        for (int mt = 0; mt < 4; mt++) {
            int r0 = m0 + warp_m * 64 + mt * 16 + og;
#pragma unroll
            for (int nt = 0; nt < 8; nt++) {
                int col = n0 + warp_n * 64 + nt * 8 + ot * 2;
                float2 lo = { acc[mt][nt][0], acc[mt][nt][1] };
                float2 hi = { acc[mt][nt][2], acc[mt][nt][3] };
                *(float2*)(Cp + (size_t)r0 * N + col) = lo;
                *(float2*)(Cp + (size_t)(r0 + 8) * N + col) = hi;
            }
        }
    }
}

// ===========================================================================
// fp16 flash attention (causal), cp.async 2-stage, register-resident P
// (FA2 style: S accumulator fragments repack directly into PV A-fragments).
// Q pre-scaled by 2^-5*log2e -> softmax uses exp2f.
// smem: Ks[2][64][144B] | Vt[2][64][144B] = 36864 B.
// ===========================================================================
#define FROWB 144
#define KTILE (64 * FROWB)                    // 9216 bytes
#define FLASH4_SMEM_BYTES (4 * KTILE)         // 36864

__device__ __forceinline__ void flash_issue(
    const __half* __restrict__ ksrc, const __half* __restrict__ vsrc,
    uint32_t ksb, uint32_t vtb, int j0, int tid)
{
#pragma unroll
    for (int jj = 0; jj < 2; jj++) {
        int slot = tid + jj * 256;         // 0..511
        int r  = slot >> 3;                // 0..63
        int c8 = slot & 7;                 // 16B chunk (8 fp16)
        uint32_t off = (uint32_t)(r * FROWB + c8 * 16);
        cp_async16(ksb + off, ksrc + (size_t)(j0 + r) * TC3 + c8 * 8);
        cp_async16(vtb + off, vsrc + (size_t)r * T_ + j0 + c8 * 8);
    }
}

__global__ __launch_bounds__(256, 2) void flash_mma_kernel()
{
    extern __shared__ char smb[];
    const uint32_t smem_u32 = smem_to_u32(smb);

    const __half* qkv = (const __half*)g_qkv;
    __half* att = (__half*)g_att;

    const int tid = threadIdx.x;
    const int lane = tid & 31;
    const int w = tid >> 5;
    const int h = blockIdx.y;
    const int b = blockIdx.z;
    const int q0 = (gridDim.x - 1 - blockIdx.x) * 128;
    const int base = b * T_ * TC3;
    const int hoff = h * D_;

    const __half* ksrc = qkv + base + hoff;
    const __half* vsrc = (const __half*)g_vT + (size_t)(b * C_ + hoff) * T_;

    const int b_row = ((lane & 16) >> 1) + (lane & 7);
    const int b_kb  = (lane >> 3) & 1;
    const int g  = lane >> 2;
    const int t  = lane & 3;
    const int t2 = t * 2;

    const int ntiles = (q0 >> 6) + 2;

    flash_issue(ksrc, vsrc, smem_u32, smem_u32 + KTILE, 0, tid);
    CP_COMMIT();

    // Q fragments: 16 regs (4 k16-steps x 4), q pre-scaled fp16 in gmem
    uint32_t qf[4][4];
    {
        const __half* qp = qkv + base + C_ + hoff;
        const size_t row0 = (size_t)(q0 + w * 16 + g) * TC3;
        const size_t row1 = row0 + (size_t)8 * TC3;
#pragma unroll
        for (int ks = 0; ks < 4; ks++) {
            int c = ks * 16 + t2;
            qf[ks][0] = *(const uint32_t*)(qp + row0 + c);
            qf[ks][1] = *(const uint32_t*)(qp + row1 + c);
            qf[ks][2] = *(const uint32_t*)(qp + row0 + c + 8);
            qf[ks][3] = *(const uint32_t*)(qp + row1 + c + 8);
        }
    }

    float o[8][4];
#pragma unroll
    for (int nt = 0; nt < 8; nt++)
#pragma unroll
        for (int k = 0; k < 4; k++) o[nt][k] = 0.f;
    float m0 = -1e30f, m1 = -1e30f, l0 = 0.f, l1 = 0.f;

    for (int i = 0; i < ntiles; i++) {
        __syncthreads();
        if (i + 1 < ntiles) {
            uint32_t sb = smem_u32 + (uint32_t)((i + 1) & 1) * (2 * KTILE);
            flash_issue(ksrc, vsrc, sb, sb + KTILE, (i + 1) * 64, tid);
            CP_COMMIT();
            CP_WAIT1();
        } else {
            CP_WAIT0();
        }
        __syncthreads();

        const uint32_t ksb = smem_u32 + (uint32_t)(i & 1) * (2 * KTILE);
        const uint32_t vtb = ksb + KTILE;
        const int j0 = i * 64;

        // S = Q @ K^T  (already in exp2 domain via q prescale)
        float s[8][4];
#pragma unroll
        for (int nt = 0; nt < 8; nt++)
#pragma unroll
            for (int k = 0; k < 4; k++) s[nt][k] = 0.f;

#pragma unroll
        for (int ks = 0; ks < 4; ks++) {
            uint32_t bf[4][4];
#pragma unroll
            for (int p = 0; p < 4; p++)
                ldmx4(bf[p], ksb + (p * 16 + b_row) * FROWB + ks * 32 + b_kb * 16);
#pragma unroll
            for (int nt = 0; nt < 8; nt++)
                mma_f16(s[nt], qf[ks], &bf[nt >> 1][(nt & 1) * 2]);
        }

        // Causal mask
        if (j0 + 64 > q0) {
            const int q_lo = q0 + w * 16 + g;
            const int q_hi = q_lo + 8;
#pragma unroll
            for (int nt = 0; nt < 8; nt++) {
                int j = j0 + nt * 8 + t2;
                if (j     > q_lo) s[nt][0] = -1e30f;
                if (j + 1 > q_lo) s[nt][1] = -1e30f;
                if (j     > q_hi) s[nt][2] = -1e30f;
                if (j + 1 > q_hi) s[nt][3] = -1e30f;
            }
        }

        // Online softmax (exp2 domain)
        float mx0 = -1e30f, mx1 = -1e30f;
#pragma unroll
        for (int nt = 0; nt < 8; nt++) {
            mx0 = fmaxf(mx0, fmaxf(s[nt][0], s[nt][1]));
            mx1 = fmaxf(mx1, fmaxf(s[nt][2], s[nt][3]));
        }
        mx0 = fmaxf(mx0, __shfl_xor_sync(0xffffffffu, mx0, 1));
        mx0 = fmaxf(mx0, __shfl_xor_sync(0xffffffffu, mx0, 2));
        mx1 = fmaxf(mx1, __shfl_xor_sync(0xffffffffu, mx1, 1));
        mx1 = fmaxf(mx1, __shfl_xor_sync(0xffffffffu, mx1, 2));
        const float mn0 = fmaxf(m0, mx0), mn1 = fmaxf(m1, mx1);
        const float al0 = exp2f(m0 - mn0), al1 = exp2f(m1 - mn1);
        m0 = mn0; m1 = mn1;

        float rs0 = 0.f, rs1 = 0.f;
#pragma unroll
        for (int nt = 0; nt < 8; nt++) {
            s[nt][0] = exp2f(s[nt][0] - mn0);
            s[nt][1] = exp2f(s[nt][1] - mn0);
            s[nt][2] = exp2f(s[nt][2] - mn1);
            s[nt][3] = exp2f(s[nt][3] - mn1);
            rs0 += s[nt][0] + s[nt][1];
            rs1 += s[nt][2] + s[nt][3];
        }
        rs0 += __shfl_xor_sync(0xffffffffu, rs0, 1);
        rs0 += __shfl_xor_sync(0xffffffffu, rs0, 2);
        rs1 += __shfl_xor_sync(0xffffffffu, rs1, 1);
        rs1 += __shfl_xor_sync(0xffffffffu, rs1, 2);
        l0 = l0 * al0 + rs0;
        l1 = l1 * al1 + rs1;
#pragma unroll
        for (int nt = 0; nt < 8; nt++) {
            o[nt][0] *= al0; o[nt][1] *= al0;
            o[nt][2] *= al1; o[nt][3] *= al1;
        }

        // Pack P into PV A-fragments (register-resident, no smem round-trip)
        uint32_t paf[4][4];
#pragma unroll
        for (int ks = 0; ks < 4; ks++) {
            paf[ks][0] = h2u(__floats2half2_rn(s[2 * ks][0],     s[2 * ks][1]));
            paf[ks][1] = h2u(__floats2half2_rn(s[2 * ks][2],     s[2 * ks][3]));
            paf[ks][2] = h2u(__floats2half2_rn(s[2 * ks + 1][0], s[2 * ks + 1][1]));
            paf[ks][3] = h2u(__floats2half2_rn(s[2 * ks + 1][2], s[2 * ks + 1][3]));
        }

        // O += P @ V
#pragma unroll
        for (int ks = 0; ks < 4; ks++) {
            uint32_t bf[4][4];
#pragma unroll
            for (int p = 0; p < 4; p++)
                ldmx4(bf[p], vtb + (p * 16 + b_row) * FROWB + ks * 32 + b_kb * 16);
#pragma unroll
            for (int nt = 0; nt < 8; nt++)
                mma_f16(o[nt], paf[ks], &bf[nt >> 1][(nt & 1) * 2]);
        }
    }

    // Epilogue: normalize, round to fp16, store
    const float inv0 = 1.f / l0, inv1 = 1.f / l1;
    const int q_lo = q0 + w * 16 + g;
    __half* arow0 = att + (size_t)(b * T_ + q_lo) * C_ + hoff;
    __half* arow1 = arow0 + (size_t)8 * C_;
#pragma unroll
    for (int nt = 0; nt < 8; nt++) {
        *(__half2*)(arow0 + nt * 8 + t2) =
            __floats2half2_rn(o[nt][0] * inv0, o[nt][1] * inv0);
        *(__half2*)(arow1 + nt * 8 + t2) =
            __floats2half2_rn(o[nt][2] * inv1, o[nt][3] * inv1);
    }
}

// ===========================================================================
// Launch
// ===========================================================================
extern "C" void kernel_launch(void* const* d_in, const int* in_sizes, int n_in,
                              void* d_out, int out_size)
{
    const float* x     = (const float*)d_in[0];   // [B,T,C]
    const float* Wqkv  = (const float*)d_in[1];   // [C,3C]
    const float* Wproj = (const float*)d_in[2];   // [C,C]
    float* out = (float*)d_out;                   // [B,T,C]

    cudaFuncSetAttribute(flash_mma_kernel,
                         cudaFuncAttributeMaxDynamicSharedMemorySize,
                         FLASH4_SMEM_BYTES);
    cudaFuncSetAttribute(mma_gemm2<0, TC3, C_>,
                         cudaFuncAttributeMaxDynamicSharedMemorySize, G2_SMEM);
    cudaFuncSetAttribute(mma_gemm2<1, C_, C_>,
                         cudaFuncAttributeMaxDynamicSharedMemorySize, G2_SMEM);

    // 0) Round x to fp16; transpose+round weights (q-rows pre-scaled)
    round_x_kernel<<<512, 256>>>(x);
    transpose_kernel<0><<<dim3(TC3 / 32, C_ / 32), dim3(32, 8)>>>(Wqkv, C_, TC3);
    transpose_kernel<1><<<dim3(C_ / 32, C_ / 32), dim3(32, 8)>>>(Wproj, C_, C_);

    // 1) k,q -> g_qkv; v -> g_vT (transposed)   (fp16 mma, 256x128 CTA)
    mma_gemm2<0, TC3, C_><<<dim3(TC3 / 128, (B_ * T_) / 256), 256, G2_SMEM>>>(nullptr);

    // 2) flash attention: g_qkv(k,q) + g_vT -> g_att   (fp16 mma, register P)
    flash_mma_kernel<<<dim3(T_ / 128, H_, B_), 256, FLASH4_SMEM_BYTES>>>();

    // 3) out = g_att @ W_proj   (fp16 mma, fp32 out)
    mma_gemm2<1, C_, C_><<<dim3(C_ / 128, (B_ * T_) / 256), 256, G2_SMEM>>>(out);
}

// round 15
// speedup vs baseline: 1.0674x; 1.0674x over previous
#include <cuda_runtime.h>
#include <cuda_fp16.h>
#include <cstdint>

// Problem constants
#define B_   4
#define T_   2048
#define C_   1024
#define H_   16
#define D_   64
#define TC3  (3 * C_)

// Scratch (allocation-free rule: __device__ globals), fp16 pipeline
__device__ __half g_qkv[B_ * T_ * TC3];    // [B,T,3C] k|q (v slot unused), q pre-scaled by 2^-5*log2e
__device__ __half g_vT[B_ * C_ * T_];      // [B][H*D][T]  V transposed
__device__ __half g_att[B_ * T_ * C_];     // [B,T,C]
__device__ __half g_xh[B_ * T_ * C_];      // [B,T,C]  x rounded to fp16
__device__ __half g_WqkvT[TC3 * C_];       // [3C, C] = W_qkv^T, q-rows pre-scaled
__device__ __half g_WprojT[C_ * C_];       // [C, C]  = W_proj^T

// ===========================================================================
// Helpers
// ===========================================================================
__device__ __forceinline__ uint32_t smem_to_u32(const void* p) {
    uint32_t a;
    asm("{ .reg .u64 t; cvta.to.shared.u64 t, %1; cvt.u32.u64 %0, t; }"
        : "=r"(a) : "l"(p));
    return a;
}

__device__ __forceinline__ void ldmx4(uint32_t* r, uint32_t addr) {
    asm volatile("ldmatrix.sync.aligned.m8n8.x4.shared.b16 {%0,%1,%2,%3}, [%4];"
                 : "=r"(r[0]), "=r"(r[1]), "=r"(r[2]), "=r"(r[3]) : "r"(addr));
}

__device__ __forceinline__ void mma_f16(float* c, const uint32_t* a,
                                        const uint32_t* b) {
    asm volatile(
        "mma.sync.aligned.m16n8k16.row.col.f32.f16.f16.f32 "
        "{%0,%1,%2,%3}, {%4,%5,%6,%7}, {%8,%9}, {%0,%1,%2,%3};"
        : "+f"(c[0]), "+f"(c[1]), "+f"(c[2]), "+f"(c[3])
        : "r"(a[0]), "r"(a[1]), "r"(a[2]), "r"(a[3]), "r"(b[0]), "r"(b[1]));
}

__device__ __forceinline__ void cp_async16(uint32_t smem_dst, const void* gsrc) {
    asm volatile("cp.async.cg.shared.global [%0], [%1], 16;"
                 :: "r"(smem_dst), "l"(gsrc));
}
#define CP_COMMIT() asm volatile("cp.async.commit_group;" ::: "memory")
#define CP_WAIT1()  asm volatile("cp.async.wait_group 1;" ::: "memory")
#define CP_WAIT0()  asm volatile("cp.async.wait_group 0;" ::: "memory")

#define SWZ(off) ((off) ^ (((off) >> 3) & 0x70))

__device__ __forceinline__ uint32_t h2u(__half2 h) {
    return *(uint32_t*)&h;
}

// ===========================================================================
// Round x to fp16 -> g_xh
// ===========================================================================
__global__ void round_x_kernel(const float* __restrict__ x)
{
    const int n8 = (B_ * T_ * C_) / 8;
    for (int i = blockIdx.x * blockDim.x + threadIdx.x; i < n8;
         i += gridDim.x * blockDim.x) {
        float4 v0 = ((const float4*)x)[2 * i];
        float4 v1 = ((const float4*)x)[2 * i + 1];
        uint4 o = { h2u(__floats2half2_rn(v0.x, v0.y)),
                    h2u(__floats2half2_rn(v0.z, v0.w)),
                    h2u(__floats2half2_rn(v1.x, v1.y)),
                    h2u(__floats2half2_rn(v1.z, v1.w)) };
        ((uint4*)g_xh)[i] = o;
    }
}

// ===========================================================================
// Weight transpose + fp16 round. MODE 0 scales q-rows (C..2C-1) by
// 2^-5 * log2(e) so S comes out of QK^T already in the exp2 domain.
// ===========================================================================
template <int MODE>
__global__ void transpose_kernel(const float* __restrict__ in, int R, int Cc)
{
    __shared__ float t[32][33];
    __half* out = (MODE == 0) ? (__half*)g_WqkvT : (__half*)g_WprojT;
    const int c0 = blockIdx.x * 32, r0 = blockIdx.y * 32;
#pragma unroll
    for (int j = threadIdx.y; j < 32; j += 8)
        t[j][threadIdx.x] = in[(size_t)(r0 + j) * Cc + c0 + threadIdx.x];
    __syncthreads();
#pragma unroll
    for (int j = threadIdx.y; j < 32; j += 8) {
        int orow = c0 + j;
        float v = t[threadIdx.x][j];
        if (MODE == 0 && orow >= C_ && orow < 2 * C_)
            v *= 0.03125f * 1.4426950408889634f;
        out[(size_t)orow * R + r0 + threadIdx.x] = __float2half_rn(v);
    }
}

// ===========================================================================
// fp16 tensor-core GEMM, cp.async 3-stage pipeline (R13 config: CTA 128x128,
// 8 warps = 2(M) x 4(N), warp tile 64x32, 128 regs, 2 CTAs/SM).
// MODE 0: A=g_xh, Bt=g_WqkvT; k,q -> g_qkv; v -> g_vT transposed.
// MODE 1: A=g_att, Bt=g_WprojT; C = param out (fp32).
// ===========================================================================
#define G2_STAGES 3
#define G2_TILE   16384
#define G2_STAGE_BYTES (2 * G2_TILE)
#define G2_SMEM   (G2_STAGES * G2_STAGE_BYTES)   // 98304

template <int K>
__device__ __forceinline__ void g2_issue(
    const __half* __restrict__ Ag, const __half* __restrict__ Bg,
    uint32_t Abuf, uint32_t Bbuf, int m0, int n0, int k0, int tid)
{
#pragma unroll
    for (int j = 0; j < 4; j++) {
        int slot = tid + j * 256;
        int row = slot >> 3;
        int f8  = slot & 7;                // 16B = 8 fp16
        uint32_t off = SWZ(row * 128 + f8 * 16);
        cp_async16(Abuf + off, Ag + (size_t)(m0 + row) * K + k0 + f8 * 8);
        cp_async16(Bbuf + off, Bg + (size_t)(n0 + row) * K + k0 + f8 * 8);
    }
}

template <int MODE, int N, int K>
__global__ __launch_bounds__(256, 2) void mma_gemm2(float* __restrict__ Cp)
{
    extern __shared__ char sm[];
    const uint32_t smem_u32 = smem_to_u32(sm);

    const __half* Ag = (MODE == 0) ? (const __half*)g_xh : (const __half*)g_att;
    const __half* Bg = (MODE == 0) ? (const __half*)g_WqkvT : (const __half*)g_WprojT;

    const int tid = threadIdx.x;
    const int lane = tid & 31;
    const int wid = tid >> 5;
    const int warp_m = wid & 1;
    const int warp_n = wid >> 1;
    const int m0 = blockIdx.y * 128;
    const int n0 = blockIdx.x * 128;

    float acc[4][4][4];
#pragma unroll
    for (int i = 0; i < 4; i++)
#pragma unroll
        for (int j = 0; j < 4; j++)
#pragma unroll
            for (int k = 0; k < 4; k++) acc[i][j][k] = 0.f;

    const int NCHUNK = K / 64;             // 16

    g2_issue<K>(Ag, Bg, smem_u32, smem_u32 + G2_TILE, m0, n0, 0, tid);
    CP_COMMIT();
    g2_issue<K>(Ag, Bg, smem_u32 + G2_STAGE_BYTES,
                smem_u32 + G2_STAGE_BYTES + G2_TILE, m0, n0, 64, tid);
    CP_COMMIT();

    const int a_row_in_tile = lane & 15;
    const int a_kblk = (lane >> 4) & 1;
    const int b_row_in_pair = ((lane & 16) >> 1) + (lane & 7);
    const int b_kblk = (lane >> 3) & 1;

    int st = 0;
    for (int i = 0; i < NCHUNK; i++) {
        CP_WAIT1();
        __syncthreads();

        if (i + 2 < NCHUNK) {
            int sn = st + 2; if (sn >= G2_STAGES) sn -= G2_STAGES;
            uint32_t base = smem_u32 + (uint32_t)sn * G2_STAGE_BYTES;
            g2_issue<K>(Ag, Bg, base, base + G2_TILE, m0, n0, (i + 2) * 64, tid);
        }
        CP_COMMIT();

        const uint32_t Abuf = smem_u32 + (uint32_t)st * G2_STAGE_BYTES;
        const uint32_t Bbuf = Abuf + G2_TILE;
#pragma unroll
        for (int ks = 0; ks < 4; ks++) {   // 4 k16-steps per 64-K chunk
            uint32_t afr[4][4];
#pragma unroll
            for (int mt = 0; mt < 4; mt++) {
                int row = warp_m * 64 + mt * 16 + a_row_in_tile;
                ldmx4(afr[mt], Abuf + SWZ(row * 128 + ks * 32 + a_kblk * 16));
            }
            uint32_t bfr[2][4];
#pragma unroll
            for (int p = 0; p < 2; p++) {
                int row = warp_n * 32 + p * 16 + b_row_in_pair;
                ldmx4(bfr[p], Bbuf + SWZ(row * 128 + ks * 32 + b_kblk * 16));
            }
#pragma unroll
            for (int mt = 0; mt < 4; mt++)
#pragma unroll
                for (int nt = 0; nt < 4; nt++)
                    mma_f16(acc[mt][nt], afr[mt], &bfr[nt >> 1][(nt & 1) * 2]);
        }

        if (++st == G2_STAGES) st = 0;
    }

    const int og = lane >> 2;
    const int ot = lane & 3;

    if (MODE == 0 && n0 >= 2 * C_) {
        // V block -> g_vT[B][H*D][T], transposed + fp16
#pragma unroll
        for (int mt = 0; mt < 4; mt++) {
            int r0 = m0 + warp_m * 64 + mt * 16 + og;
            int bb = r0 >> 11;
            int tt = r0 & (T_ - 1);
#pragma unroll
            for (int nt = 0; nt < 4; nt++) {
                int hd = n0 + warp_n * 32 + nt * 8 + ot * 2 - 2 * C_;
                __half* v0p = (__half*)g_vT + (size_t)(bb * C_ + hd) * T_;
                __half* v1p = v0p + T_;
                v0p[tt]     = __float2half_rn(acc[mt][nt][0]);
                v1p[tt]     = __float2half_rn(acc[mt][nt][1]);
                v0p[tt + 8] = __float2half_rn(acc[mt][nt][2]);
                v1p[tt + 8] = __float2half_rn(acc[mt][nt][3]);
            }
        }
    } else if (MODE == 0) {
        __half* Cg = (__half*)g_qkv;
#pragma unroll
        for (int mt = 0; mt < 4; mt++) {
            int r0 = m0 + warp_m * 64 + mt * 16 + og;
#pragma unroll
            for (int nt = 0; nt < 4; nt++) {
                int col = n0 + warp_n * 32 + nt * 8 + ot * 2;
                *(__half2*)(Cg + (size_t)r0 * N + col) =
                    __floats2half2_rn(acc[mt][nt][0], acc[mt][nt][1]);
                *(__half2*)(Cg + (size_t)(r0 + 8) * N + col) =
                    __floats2half2_rn(acc[mt][nt][2], acc[mt][nt][3]);
            }
        }
    } else {
#pragma unroll
        for (int mt = 0; mt < 4; mt++) {
            int r0 = m0 + warp_m * 64 + mt * 16 + og;
#pragma unroll
            for (int nt = 0; nt < 4; nt++) {
                int col = n0 + warp_n * 32 + nt * 8 + ot * 2;
                float2 lo = { acc[mt][nt][0], acc[mt][nt][1] };
                float2 hi = { acc[mt][nt][2], acc[mt][nt][3] };
                *(float2*)(Cp + (size_t)r0 * N + col) = lo;
                *(float2*)(Cp + (size_t)(r0 + 8) * N + col) = hi;
            }
        }
    }
}

// ===========================================================================
// fp16 flash attention (causal), cp.async 2-stage, register-resident P
// (FA2 style). Q pre-scaled by 2^-5*log2e -> softmax uses exp2f.
// smem: Ks[2][64][144B] | Vt[2][64][144B] = 36864 B.
// ===========================================================================
#define FROWB 144
#define KTILE (64 * FROWB)                    // 9216 bytes
#define FLASH4_SMEM_BYTES (4 * KTILE)         // 36864

__device__ __forceinline__ void flash_issue(
    const __half* __restrict__ ksrc, const __half* __restrict__ vsrc,
    uint32_t ksb, uint32_t vtb, int j0, int tid)
{
#pragma unroll
    for (int jj = 0; jj < 2; jj++) {
        int slot = tid + jj * 256;         // 0..511
        int r  = slot >> 3;                // 0..63
        int c8 = slot & 7;                 // 16B chunk (8 fp16)
        uint32_t off = (uint32_t)(r * FROWB + c8 * 16);
        cp_async16(ksb + off, ksrc + (size_t)(j0 + r) * TC3 + c8 * 8);
        cp_async16(vtb + off, vsrc + (size_t)r * T_ + j0 + c8 * 8);
    }
}

__global__ __launch_bounds__(256, 2) void flash_mma_kernel()
{
    extern __shared__ char smb[];
    const uint32_t smem_u32 = smem_to_u32(smb);

    const __half* qkv = (const __half*)g_qkv;
    __half* att = (__half*)g_att;

    const int tid = threadIdx.x;
    const int lane = tid & 31;
    const int w = tid >> 5;
    const int h = blockIdx.y;
    const int b = blockIdx.z;
    const int q0 = (gridDim.x - 1 - blockIdx.x) * 128;
    const int base = b * T_ * TC3;
    const int hoff = h * D_;

    const __half* ksrc = qkv + base + hoff;
    const __half* vsrc = (const __half*)g_vT + (size_t)(b * C_ + hoff) * T_;

    const int b_row = ((lane & 16) >> 1) + (lane & 7);
    const int b_kb  = (lane >> 3) & 1;
    const int g  = lane >> 2;
    const int t  = lane & 3;
    const int t2 = t * 2;

    const int ntiles = (q0 >> 6) + 2;

    flash_issue(ksrc, vsrc, smem_u32, smem_u32 + KTILE, 0, tid);
    CP_COMMIT();

    // Q fragments: 16 regs (4 k16-steps x 4), q pre-scaled fp16 in gmem
    uint32_t qf[4][4];
    {
        const __half* qp = qkv + base + C_ + hoff;
        const size_t row0 = (size_t)(q0 + w * 16 + g) * TC3;
        const size_t row1 = row0 + (size_t)8 * TC3;
#pragma unroll
        for (int ks = 0; ks < 4; ks++) {
            int c = ks * 16 + t2;
            qf[ks][0] = *(const uint32_t*)(qp + row0 + c);
            qf[ks][1] = *(const uint32_t*)(qp + row1 + c);
            qf[ks][2] = *(const uint32_t*)(qp + row0 + c + 8);
            qf[ks][3] = *(const uint32_t*)(qp + row1 + c + 8);
        }
    }

    float o[8][4];
#pragma unroll
    for (int nt = 0; nt < 8; nt++)
#pragma unroll
        for (int k = 0; k < 4; k++) o[nt][k] = 0.f;
    float m0 = -1e30f, m1 = -1e30f, l0 = 0.f, l1 = 0.f;

    for (int i = 0; i < ntiles; i++) {
        __syncthreads();
        if (i + 1 < ntiles) {
            uint32_t sb = smem_u32 + (uint32_t)((i + 1) & 1) * (2 * KTILE);
            flash_issue(ksrc, vsrc, sb, sb + KTILE, (i + 1) * 64, tid);
            CP_COMMIT();
            CP_WAIT1();
        } else {
            CP_WAIT0();
        }
        __syncthreads();

        const uint32_t ksb = smem_u32 + (uint32_t)(i & 1) * (2 * KTILE);
        const uint32_t vtb = ksb + KTILE;
        const int j0 = i * 64;

        // S = Q @ K^T  (already in exp2 domain via q prescale)
        float s[8][4];
#pragma unroll
        for (int nt = 0; nt < 8; nt++)
#pragma unroll
            for (int k = 0; k < 4; k++) s[nt][k] = 0.f;

#pragma unroll
        for (int ks = 0; ks < 4; ks++) {
            uint32_t bf[4][4];
#pragma unroll
            for (int p = 0; p < 4; p++)
                ldmx4(bf[p], ksb + (p * 16 + b_row) * FROWB + ks * 32 + b_kb * 16);
#pragma unroll
            for (int nt = 0; nt < 8; nt++)
                mma_f16(s[nt], qf[ks], &bf[nt >> 1][(nt & 1) * 2]);
        }

        // Causal mask
        if (j0 + 64 > q0) {
            const int q_lo = q0 + w * 16 + g;
            const int q_hi = q_lo + 8;
#pragma unroll
            for (int nt = 0; nt < 8; nt++) {
                int j = j0 + nt * 8 + t2;
                if (j     > q_lo) s[nt][0] = -1e30f;
                if (j + 1 > q_lo) s[nt][1] = -1e30f;
                if (j     > q_hi) s[nt][2] = -1e30f;
                if (j + 1 > q_hi) s[nt][3] = -1e30f;
            }
        }

        // Online softmax (exp2 domain)
        float mx0 = -1e30f, mx1 = -1e30f;
#pragma unroll
        for (int nt = 0; nt < 8; nt++) {
            mx0 = fmaxf(mx0, fmaxf(s[nt][0], s[nt][1]));
            mx1 = fmaxf(mx1, fmaxf(s[nt][2], s[nt][3]));
        }
        mx0 = fmaxf(mx0, __shfl_xor_sync(0xffffffffu, mx0, 1));
        mx0 = fmaxf(mx0, __shfl_xor_sync(0xffffffffu, mx0, 2));
        mx1 = fmaxf(mx1, __shfl_xor_sync(0xffffffffu, mx1, 1));
        mx1 = fmaxf(mx1, __shfl_xor_sync(0xffffffffu, mx1, 2));
        const float mn0 = fmaxf(m0, mx0), mn1 = fmaxf(m1, mx1);
        const float al0 = exp2f(m0 - mn0), al1 = exp2f(m1 - mn1);
        m0 = mn0; m1 = mn1;

        float rs0 = 0.f, rs1 = 0.f;
#pragma unroll
        for (int nt = 0; nt < 8; nt++) {
            s[nt][0] = exp2f(s[nt][0] - mn0);
            s[nt][1] = exp2f(s[nt][1] - mn0);
            s[nt][2] = exp2f(s[nt][2] - mn1);
            s[nt][3] = exp2f(s[nt][3] - mn1);
            rs0 += s[nt][0] + s[nt][1];
            rs1 += s[nt][2] + s[nt][3];
        }
        rs0 += __shfl_xor_sync(0xffffffffu, rs0, 1);
        rs0 += __shfl_xor_sync(0xffffffffu, rs0, 2);
        rs1 += __shfl_xor_sync(0xffffffffu, rs1, 1);
        rs1 += __shfl_xor_sync(0xffffffffu, rs1, 2);
        l0 = l0 * al0 + rs0;
        l1 = l1 * al1 + rs1;
#pragma unroll
        for (int nt = 0; nt < 8; nt++) {
            o[nt][0] *= al0; o[nt][1] *= al0;
            o[nt][2] *= al1; o[nt][3] *= al1;
        }

        // Pack P into PV A-fragments (register-resident, no smem round-trip)
        uint32_t paf[4][4];
#pragma unroll
        for (int ks = 0; ks < 4; ks++) {
            paf[ks][0] = h2u(__floats2half2_rn(s[2 * ks][0],     s[2 * ks][1]));
            paf[ks][1] = h2u(__floats2half2_rn(s[2 * ks][2],     s[2 * ks][3]));
            paf[ks][2] = h2u(__floats2half2_rn(s[2 * ks + 1][0], s[2 * ks + 1][1]));
            paf[ks][3] = h2u(__floats2half2_rn(s[2 * ks + 1][2], s[2 * ks + 1][3]));
        }

        // O += P @ V
#pragma unroll
        for (int ks = 0; ks < 4; ks++) {
            uint32_t bf[4][4];
#pragma unroll
            for (int p = 0; p < 4; p++)
                ldmx4(bf[p], vtb + (p * 16 + b_row) * FROWB + ks * 32 + b_kb * 16);
#pragma unroll
            for (int nt = 0; nt < 8; nt++)
                mma_f16(o[nt], paf[ks], &bf[nt >> 1][(nt & 1) * 2]);
        }
    }

    // Epilogue: normalize, round to fp16, store
    const float inv0 = 1.f / l0, inv1 = 1.f / l1;
    const int q_lo = q0 + w * 16 + g;
    __half* arow0 = att + (size_t)(b * T_ + q_lo) * C_ + hoff;
    __half* arow1 = arow0 + (size_t)8 * C_;
#pragma unroll
    for (int nt = 0; nt < 8; nt++) {
        *(__half2*)(arow0 + nt * 8 + t2) =
            __floats2half2_rn(o[nt][0] * inv0, o[nt][1] * inv0);
        *(__half2*)(arow1 + nt * 8 + t2) =
            __floats2half2_rn(o[nt][2] * inv1, o[nt][3] * inv1);
    }
}

// ===========================================================================
// Launch
// ===========================================================================
extern "C" void kernel_launch(void* const* d_in, const int* in_sizes, int n_in,
                              void* d_out, int out_size)
{
    const float* x     = (const float*)d_in[0];   // [B,T,C]
    const float* Wqkv  = (const float*)d_in[1];   // [C,3C]
    const float* Wproj = (const float*)d_in[2];   // [C,C]
    float* out = (float*)d_out;                   // [B,T,C]

    cudaFuncSetAttribute(flash_mma_kernel,
                         cudaFuncAttributeMaxDynamicSharedMemorySize,
                         FLASH4_SMEM_BYTES);
    cudaFuncSetAttribute(mma_gemm2<0, TC3, C_>,
                         cudaFuncAttributeMaxDynamicSharedMemorySize, G2_SMEM);
    cudaFuncSetAttribute(mma_gemm2<1, C_, C_>,
                         cudaFuncAttributeMaxDynamicSharedMemorySize, G2_SMEM);

    // 0) Round x to fp16; transpose+round weights (q-rows pre-scaled)
    round_x_kernel<<<512, 256>>>(x);
    transpose_kernel<0><<<dim3(TC3 / 32, C_ / 32), dim3(32, 8)>>>(Wqkv, C_, TC3);
    transpose_kernel<1><<<dim3(C_ / 32, C_ / 32), dim3(32, 8)>>>(Wproj, C_, C_);

    // 1) k,q -> g_qkv; v -> g_vT (transposed)   (fp16 mma, 128x128 CTA)
    mma_gemm2<0, TC3, C_><<<dim3(TC3 / 128, (B_ * T_) / 128), 256, G2_SMEM>>>(nullptr);

    // 2) flash attention: g_qkv(k,q) + g_vT -> g_att   (fp16 mma, register P)
    flash_mma_kernel<<<dim3(T_ / 128, H_, B_), 256, FLASH4_SMEM_BYTES>>>();

    // 3) out = g_att @ W_proj   (fp16 mma, fp32 out)
    mma_gemm2<1, C_, C_><<<dim3(C_ / 128, (B_ * T_) / 128), 256, G2_SMEM>>>(out);
}